// round 13
// baseline (speedup 1.0000x reference)
#include <cuda_runtime.h>
#include <cuda_bf16.h>
#include <cstdint>
#include <cstddef>

// ---------------------------------------------------------------------------
// PhysicsInformedAttention — Round 13: GEMMs at 2 CTAs/SM (barrier overlap),
// attention unchanged from R12 (3 CTAs/SM, Bc=32, register P).
// B=2, S=2048, HIDDEN=1024, NH=16, D=64, SA=2051. Physics biases cancel.
// ---------------------------------------------------------------------------

#define Bz 2
#define SEQ 2048
#define SA 2051
#define HID 1024
#define NHEADS 16
#define HD 64
#define MAUG (Bz * SA)   /* 4102 */
#define MOUT (Bz * SEQ)  /* 4096 */

__device__ __nv_bfloat16 g_augb[2 * MAUG * HID];
__device__ __nv_bfloat16 g_Wb  [4 * HID * HID];    // W bf16 [k][n] for q,k,v,o
__device__ __nv_bfloat16 g_Qb  [2 * MAUG * HID];
__device__ __nv_bfloat16 g_Kb  [2 * MAUG * HID];
__device__ __nv_bfloat16 g_Vb  [2 * MAUG * HID];
__device__ __nv_bfloat16 g_attb[2 * MOUT * HID];
__device__ float         g_O   [2 * MOUT * HID];

// ----------------------------- helpers -------------------------------------
__device__ __forceinline__ uint32_t pk(float a, float b) {
    __nv_bfloat162 h = __floats2bfloat162_rn(a, b);
    return *reinterpret_cast<uint32_t*>(&h);
}
__device__ __forceinline__ void ldsm4(uint32_t& r0, uint32_t& r1, uint32_t& r2,
                                      uint32_t& r3, const void* p) {
    uint32_t a = (uint32_t)__cvta_generic_to_shared(p);
    asm volatile("ldmatrix.sync.aligned.m8n8.x4.shared.b16 {%0,%1,%2,%3}, [%4];"
                 : "=r"(r0), "=r"(r1), "=r"(r2), "=r"(r3) : "r"(a));
}
__device__ __forceinline__ void ldsm4t(uint32_t& r0, uint32_t& r1, uint32_t& r2,
                                       uint32_t& r3, const void* p) {
    uint32_t a = (uint32_t)__cvta_generic_to_shared(p);
    asm volatile("ldmatrix.sync.aligned.m8n8.x4.trans.shared.b16 {%0,%1,%2,%3}, [%4];"
                 : "=r"(r0), "=r"(r1), "=r"(r2), "=r"(r3) : "r"(a));
}
__device__ __forceinline__ void mma_bf16(float* d, const uint32_t* a,
                                         const uint32_t* b) {
    asm volatile(
        "mma.sync.aligned.m16n8k16.row.col.f32.bf16.bf16.f32 "
        "{%0,%1,%2,%3}, {%4,%5,%6,%7}, {%8,%9}, {%0,%1,%2,%3};\n"
        : "+f"(d[0]), "+f"(d[1]), "+f"(d[2]), "+f"(d[3])
        : "r"(a[0]), "r"(a[1]), "r"(a[2]), "r"(a[3]), "r"(b[0]), "r"(b[1]));
}
__device__ __forceinline__ void cpa16(uint32_t dst, const void* src, bool ok) {
    int sz = ok ? 16 : 0;
    asm volatile("cp.async.cg.shared.global [%0], [%1], 16, %2;"
                 :: "r"(dst), "l"(src), "r"(sz) : "memory");
}
#define CPA_COMMIT() asm volatile("cp.async.commit_group;" ::: "memory")
#define CPA_WAIT1()  asm volatile("cp.async.wait_group 1;" ::: "memory")

// ---------------------------------------------------------------------------
// Kernel 0: fp32 -> bf16 convert of W (4 matrices)
// ---------------------------------------------------------------------------
__global__ __launch_bounds__(256) void conv_w(
    const float* __restrict__ Wq, const float* __restrict__ Wk,
    const float* __restrict__ Wv, const float* __restrict__ Wo)
{
    int i4 = blockIdx.x * 256 + threadIdx.x;
    int w  = i4 >> 18;
    int e  = i4 & 262143;
    const float* W = (w == 0) ? Wq : (w == 1) ? Wk : (w == 2) ? Wv : Wo;
    float4 v = ((const float4*)W)[e];
    *(uint2*)(g_Wb + (size_t)w * HID * HID + (size_t)e * 4) =
        make_uint2(pk(v.x, v.y), pk(v.z, v.w));
}

// ---------------------------------------------------------------------------
// Kernel 1: build augmented tensors -> bf16
// ---------------------------------------------------------------------------
__global__ __launch_bounds__(256) void build_aug(
    const float* __restrict__ cnn, const float* __restrict__ llm,
    const float* __restrict__ ee, const float* __restrict__ me,
    const float* __restrict__ pe)
{
    int row = blockIdx.x;
    int src = row / MAUG;
    int rem = row - src * MAUG;
    int b   = rem / SA;
    int s   = rem - b * SA;
    const float* p;
    if (s < SEQ) p = (src ? llm : cnn) + ((size_t)(b * SEQ + s)) * HID;
    else         p = (s == SEQ ? ee : (s == SEQ + 1 ? me : pe));
    __nv_bfloat16* dst = g_augb + (size_t)row * HID;
    int t = threadIdx.x;
    float4 v = *(const float4*)(p + t * 4);
    *(uint2*)(dst + t * 4) = make_uint2(pk(v.x, v.y), pk(v.z, v.w));
}

// ---------------------------------------------------------------------------
// bf16 GEMM: C[M,1024] = A[M,1024] @ W[1024,1024] + bias
// 128x256 block, kc=32, 8 warps 2x4, warp tile 64x64, 3-stage cp.async,
// 2 CTAs/SM (barrier overlap between co-resident CTAs).
// ---------------------------------------------------------------------------
#define AS_STRIDE 40
#define BS_STRIDE 264
#define AS_STG (128 * AS_STRIDE)
#define BS_STG (32 * BS_STRIDE)
#define GEMM_SMEM ((3 * AS_STG + 3 * BS_STG) * 2)

template <bool OUT_BF16>
__device__ __forceinline__ void gemm_body(
    const __nv_bfloat16* __restrict__ A, const __nv_bfloat16* __restrict__ Wb,
    const float* __restrict__ bias, void* Cout, int M)
{
    extern __shared__ char smraw[];
    __nv_bfloat16* Asm = (__nv_bfloat16*)smraw;          // [3][128][40]
    __nv_bfloat16* Bsm = Asm + 3 * AS_STG;               // [3][32][264]
    const uint32_t As_u = (uint32_t)__cvta_generic_to_shared(Asm);
    const uint32_t Bs_u = (uint32_t)__cvta_generic_to_shared(Bsm);

    const int tid  = threadIdx.x;
    const int lane = tid & 31;
    const int warp = tid >> 5;
    const int q = lane >> 2, r = lane & 3;
    const int g = lane >> 3, L = lane & 7;
    const int wm = warp >> 2, wn = warp & 3;
    const int bx = blockIdx.x, by = blockIdx.y;

    const int arow = tid >> 2, aseg = tid & 3;
    const int brow = tid >> 5, bseg = tid & 31;

    float acc[4][8][4];
#pragma unroll
    for (int i = 0; i < 4; i++)
#pragma unroll
        for (int j = 0; j < 8; j++)
#pragma unroll
            for (int k = 0; k < 4; k++) acc[i][j][k] = 0.f;

    auto fill = [&](int c, int s) {
#pragma unroll
        for (int i = 0; i < 2; i++) {
            const int row = arow + i * 64;
            const int gr  = by * 128 + row;
            const bool ok = gr < M;
            const __nv_bfloat16* src =
                A + (size_t)(ok ? gr : (M - 1)) * HID + c * 32 + aseg * 8;
            cpa16(As_u + (uint32_t)(s * AS_STG + row * AS_STRIDE + aseg * 8) * 2,
                  src, ok);
        }
#pragma unroll
        for (int i = 0; i < 4; i++) {
            const int row = brow + i * 8;
            const __nv_bfloat16* src =
                Wb + (size_t)(c * 32 + row) * HID + bx * 256 + bseg * 8;
            cpa16(Bs_u + (uint32_t)(s * BS_STG + row * BS_STRIDE + bseg * 8) * 2,
                  src, true);
        }
    };

    fill(0, 0); CPA_COMMIT();
    fill(1, 1); CPA_COMMIT();

    int st = 0;
    for (int it = 0; it < 32; it++) {
        CPA_WAIT1();
        __syncthreads();
        if (it + 2 < 32) {
            int s2 = st + 2; if (s2 >= 3) s2 -= 3;
            fill(it + 2, s2);
        }
        CPA_COMMIT();

        const __nv_bfloat16* Aps = Asm + st * AS_STG;
        const __nv_bfloat16* Bps = Bsm + st * BS_STG;
#pragma unroll
        for (int ks = 0; ks < 2; ks++) {
            const int k0 = ks * 16;
            uint32_t af[4][4];
#pragma unroll
            for (int mt = 0; mt < 4; mt++) {
                const int row = wm * 64 + mt * 16 + (g & 1) * 8 + L;
                ldsm4(af[mt][0], af[mt][1], af[mt][2], af[mt][3],
                      Aps + row * AS_STRIDE + k0 + (g >> 1) * 8);
            }
            uint32_t bf[8][2];
#pragma unroll
            for (int np = 0; np < 4; np++) {
                const int row = k0 + (g & 1) * 8 + L;
                const int col = wn * 64 + np * 16 + (g >> 1) * 8;
                uint32_t r0, r1, r2, r3;
                ldsm4t(r0, r1, r2, r3, Bps + row * BS_STRIDE + col);
                bf[np * 2][0] = r0; bf[np * 2][1] = r1;
                bf[np * 2 + 1][0] = r2; bf[np * 2 + 1][1] = r3;
            }
#pragma unroll
            for (int mt = 0; mt < 4; mt++)
#pragma unroll
                for (int nt = 0; nt < 8; nt++)
                    mma_bf16(acc[mt][nt], af[mt], bf[nt]);
        }
        if (++st >= 3) st = 0;
    }

    // epilogue
#pragma unroll
    for (int mt = 0; mt < 4; mt++) {
#pragma unroll
        for (int nt = 0; nt < 8; nt++) {
            const int row0 = by * 128 + wm * 64 + mt * 16 + q;
            const int col  = bx * 256 + wn * 64 + nt * 8 + 2 * r;
            const float b0 = bias[col], b1 = bias[col + 1];
            const float* a = acc[mt][nt];
            if constexpr (OUT_BF16) {
                __nv_bfloat16* C = (__nv_bfloat16*)Cout;
                if (row0 < M)
                    *(uint32_t*)(C + (size_t)row0 * HID + col) = pk(a[0] + b0, a[1] + b1);
                if (row0 + 8 < M)
                    *(uint32_t*)(C + (size_t)(row0 + 8) * HID + col) = pk(a[2] + b0, a[3] + b1);
            } else {
                float* C = (float*)Cout;
                if (row0 < M)
                    *(float2*)(C + (size_t)row0 * HID + col) =
                        make_float2(a[0] + b0, a[1] + b1);
                if (row0 + 8 < M)
                    *(float2*)(C + (size_t)(row0 + 8) * HID + col) =
                        make_float2(a[2] + b0, a[3] + b1);
            }
        }
    }
}

__global__ __launch_bounds__(256, 2) void qkv_gemm(
    const float* __restrict__ bq, const float* __restrict__ bk,
    const float* __restrict__ bv)
{
    int z = blockIdx.z;
    int src = z / 3, w = z - src * 3;
    const __nv_bfloat16* A = g_augb + (size_t)src * MAUG * HID;
    const __nv_bfloat16* Wb = g_Wb + (size_t)w * HID * HID;
    const float* bp = (w == 0) ? bq : (w == 1) ? bk : bv;
    __nv_bfloat16* C = ((w == 0) ? g_Qb : (w == 1) ? g_Kb : g_Vb)
                       + (size_t)src * MAUG * HID;
    gemm_body<true>(A, Wb, bp, C, MAUG);
}

__global__ __launch_bounds__(256, 2) void oproj_gemm(const float* __restrict__ bo)
{
    int dir = blockIdx.z;
    gemm_body<false>(g_attb + (size_t)dir * MOUT * HID,
                     g_Wb + (size_t)3 * HID * HID, bo,
                     g_O + (size_t)dir * MOUT * HID, MOUT);
}

// ---------------------------------------------------------------------------
// Flash attention: 4 warps x 32 q-rows, Bc=32, register-resident P,
// 3-stage cp.async, static smem, 3 CTAs/SM (unchanged from R12).
// ---------------------------------------------------------------------------
__global__ __launch_bounds__(128, 3) void attn_bf16()
{
    __shared__ alignas(16) __nv_bfloat16 Kst[3][32][72];
    __shared__ alignas(16) __nv_bfloat16 Vst[3][32][72];

    const int tid  = threadIdx.x;
    const int lane = tid & 31;
    const int warp = tid >> 5;        // 0..3, owns q rows [32w, 32w+32)
    const int q = lane >> 2, r = lane & 3;
    const int g = lane >> 3, L = lane & 7;
    const int m0 = warp * 32;

    const int qt  = blockIdx.x;
    const int h   = blockIdx.y;
    const int dir = blockIdx.z >> 1;
    const int b   = blockIdx.z & 1;

    const __nv_bfloat16* qp =
        g_Qb + ((size_t)((dir * Bz + b) * SA) + qt * 128 + m0) * HID + h * HD;
    const size_t kvbase = ((size_t)(((dir ^ 1) * Bz + b) * SA)) * HID + h * HD;

    const uint32_t K_u = (uint32_t)__cvta_generic_to_shared(&Kst[0][0][0]);
    const uint32_t V_u = (uint32_t)__cvta_generic_to_shared(&Vst[0][0][0]);
    const int frow = tid >> 2, fseg = tid & 3;   // 128 thr: row 0..31, 2 segs each

    auto fill = [&](int t, int s) {
        const int key = t * 32 + frow;
        const bool ok = key < SA;
        const size_t rb = kvbase + (size_t)(ok ? key : 0) * HID;
#pragma unroll
        for (int i = 0; i < 2; i++) {
            const int seg = fseg + i * 4;
            const uint32_t d = (uint32_t)(s * 32 * 72 + frow * 72 + seg * 8) * 2;
            cpa16(K_u + d, g_Kb + rb + seg * 8, ok);
            cpa16(V_u + d, g_Vb + rb + seg * 8, ok);
        }
    };

    // persistent Q fragments (2 m-tiles x 4 k-steps)
    uint32_t aQ[2][4][4];
#pragma unroll
    for (int mt = 0; mt < 2; mt++) {
        const __nv_bfloat16* qpm = qp + (size_t)(mt * 16) * HID;
#pragma unroll
        for (int ks = 0; ks < 4; ks++) {
            const int c0 = ks * 16 + 2 * r;
            aQ[mt][ks][0] = *(const uint32_t*)(qpm + (size_t)q * HID + c0);
            aQ[mt][ks][1] = *(const uint32_t*)(qpm + (size_t)(q + 8) * HID + c0);
            aQ[mt][ks][2] = *(const uint32_t*)(qpm + (size_t)q * HID + c0 + 8);
            aQ[mt][ks][3] = *(const uint32_t*)(qpm + (size_t)(q + 8) * HID + c0 + 8);
        }
    }

    float o[2][8][4];
#pragma unroll
    for (int mt = 0; mt < 2; mt++)
#pragma unroll
        for (int i = 0; i < 8; i++)
#pragma unroll
            for (int j = 0; j < 4; j++) o[mt][i][j] = 0.f;
    float l0[2] = {0.f, 0.f}, l1[2] = {0.f, 0.f};

    fill(0, 0); CPA_COMMIT();
    fill(1, 1); CPA_COMMIT();

    int st = 0;
    for (int kt = 0; kt < 65; kt++) {
        CPA_WAIT1();
        __syncthreads();
        if (kt + 2 < 65) {
            int s2 = st + 2; if (s2 >= 3) s2 -= 3;
            fill(kt + 2, s2);
        }
        CPA_COMMIT();

        // ---- S = Q @ K^T : 32 q x 32 keys per warp; K frags shared by mt ----
        float sAcc[2][4][4];
#pragma unroll
        for (int mt = 0; mt < 2; mt++)
#pragma unroll
            for (int i = 0; i < 4; i++)
#pragma unroll
                for (int j = 0; j < 4; j++) sAcc[mt][i][j] = 0.f;
#pragma unroll
        for (int ks = 0; ks < 4; ks++) {
            const int k0 = ks * 16;
            uint32_t bk_[4][2];
#pragma unroll
            for (int half = 0; half < 2; half++) {
                const int row = half * 16 + (g >> 1) * 8 + L;
                const int col = k0 + (g & 1) * 8;
                uint32_t r0, r1, r2, r3;
                ldsm4(r0, r1, r2, r3, &Kst[st][row][col]);
                bk_[half * 2][0] = r0; bk_[half * 2][1] = r1;
                bk_[half * 2 + 1][0] = r2; bk_[half * 2 + 1][1] = r3;
            }
#pragma unroll
            for (int mt = 0; mt < 2; mt++)
#pragma unroll
                for (int nt = 0; nt < 4; nt++)
                    mma_bf16(sAcc[mt][nt], aQ[mt][ks], bk_[nt]);
        }

        // ---- P = exp(S/8) in registers -> A fragments ----
        uint32_t aP[2][2][4];
        if (kt < 64) {
#pragma unroll
            for (int mt = 0; mt < 2; mt++) {
#pragma unroll
                for (int nt = 0; nt < 4; nt++) {
                    float e0 = __expf(sAcc[mt][nt][0] * 0.125f);
                    float e1 = __expf(sAcc[mt][nt][1] * 0.125f);
                    float e2 = __expf(sAcc[mt][nt][2] * 0.125f);
                    float e3 = __expf(sAcc[mt][nt][3] * 0.125f);
                    l0[mt] += e0 + e1;
                    l1[mt] += e2 + e3;
                    aP[mt][nt >> 1][(nt & 1) ? 2 : 0] = pk(e0, e1);
                    aP[mt][nt >> 1][(nt & 1) ? 3 : 1] = pk(e2, e3);
                }
            }
        } else {
            const int kb = kt * 32;
#pragma unroll
            for (int mt = 0; mt < 2; mt++) {
#pragma unroll
                for (int nt = 0; nt < 4; nt++) {
                    const int key0 = kb + nt * 8 + 2 * r;
                    float e0 = (key0     < SA) ? __expf(sAcc[mt][nt][0] * 0.125f) : 0.f;
                    float e1 = (key0 + 1 < SA) ? __expf(sAcc[mt][nt][1] * 0.125f) : 0.f;
                    float e2 = (key0     < SA) ? __expf(sAcc[mt][nt][2] * 0.125f) : 0.f;
                    float e3 = (key0 + 1 < SA) ? __expf(sAcc[mt][nt][3] * 0.125f) : 0.f;
                    l0[mt] += e0 + e1;
                    l1[mt] += e2 + e3;
                    aP[mt][nt >> 1][(nt & 1) ? 2 : 0] = pk(e0, e1);
                    aP[mt][nt >> 1][(nt & 1) ? 3 : 1] = pk(e2, e3);
                }
            }
        }

        // ---- O += P @ V : V frags shared by mt ----
#pragma unroll
        for (int p = 0; p < 2; p++) {
            const int k0 = p * 16;
#pragma unroll
            for (int db = 0; db < 4; db++) {
                const int row = k0 + (g & 1) * 8 + L;
                const int col = db * 16 + (g >> 1) * 8;
                uint32_t r0, r1, r2, r3;
                ldsm4t(r0, r1, r2, r3, &Vst[st][row][col]);
                uint32_t b0[2] = {r0, r1};
                uint32_t b1[2] = {r2, r3};
#pragma unroll
                for (int mt = 0; mt < 2; mt++) {
                    mma_bf16(o[mt][db * 2], aP[mt][p], b0);
                    mma_bf16(o[mt][db * 2 + 1], aP[mt][p], b1);
                }
            }
        }
        if (++st >= 3) st = 0;
    }

    // ---- finalize per m-tile: quad row-sums, scale, bf16 store ----
#pragma unroll
    for (int mt = 0; mt < 2; mt++) {
        float a0 = l0[mt], a1 = l1[mt];
        a0 += __shfl_xor_sync(0xFFFFFFFFu, a0, 1);
        a0 += __shfl_xor_sync(0xFFFFFFFFu, a0, 2);
        a1 += __shfl_xor_sync(0xFFFFFFFFu, a1, 1);
        a1 += __shfl_xor_sync(0xFFFFFFFFu, a1, 2);
        const float inv0 = 1.0f / a0;
        const float inv1 = 1.0f / a1;

        __nv_bfloat16* op =
            g_attb + ((size_t)((dir * Bz + b) * SEQ) + qt * 128 + m0 + mt * 16) * HID
            + h * HD;
#pragma unroll
        for (int nt2 = 0; nt2 < 8; nt2++) {
            const int c = nt2 * 8 + 2 * r;
            *(uint32_t*)(op + (size_t)q * HID + c) =
                pk(o[mt][nt2][0] * inv0, o[mt][nt2][1] * inv0);
            *(uint32_t*)(op + (size_t)(q + 8) * HID + c) =
                pk(o[mt][nt2][2] * inv1, o[mt][nt2][3] * inv1);
        }
    }
}

// ---------------------------------------------------------------------------
// Kernel 4: residual + LayerNorm (fp32)
// ---------------------------------------------------------------------------
__global__ __launch_bounds__(256) void resid_ln(
    const float* __restrict__ cnn, const float* __restrict__ llm,
    const float* __restrict__ gamma, const float* __restrict__ beta,
    float* __restrict__ out)
{
    int row = blockIdx.x;
    int dir = row >> 12;
    int b   = (row >> 11) & 1;
    int s   = row & (SEQ - 1);
    const float* resid = (dir ? llm : cnn) + ((size_t)(b * SEQ + s)) * HID;
    const float* op = g_O + (size_t)row * HID;
    int t = threadIdx.x;

    float4 rv = *(const float4*)(resid + t * 4);
    float4 ov = *(const float4*)(op + t * 4);
    float x0 = rv.x + ov.x, x1 = rv.y + ov.y, x2 = rv.z + ov.z, x3 = rv.w + ov.w;
    float s1 = (x0 + x1) + (x2 + x3);
    float s2 = x0 * x0 + x1 * x1 + x2 * x2 + x3 * x3;
#pragma unroll
    for (int off = 16; off; off >>= 1) {
        s1 += __shfl_xor_sync(0xFFFFFFFFu, s1, off);
        s2 += __shfl_xor_sync(0xFFFFFFFFu, s2, off);
    }
    __shared__ float sm1[8], sm2[8];
    int wp = t >> 5, lane = t & 31;
    if (lane == 0) { sm1[wp] = s1; sm2[wp] = s2; }
    __syncthreads();
    if (t == 0) {
        float a = 0.f, c = 0.f;
#pragma unroll
        for (int i = 0; i < 8; i++) { a += sm1[i]; c += sm2[i]; }
        sm1[0] = a; sm2[0] = c;
    }
    __syncthreads();
    float mean = sm1[0] * (1.0f / HID);
    float var  = sm2[0] * (1.0f / HID) - mean * mean;
    float rstd = rsqrtf(var + 1e-5f);

    float4 gm = *(const float4*)(gamma + t * 4);
    float4 be = *(const float4*)(beta + t * 4);
    float4 y;
    y.x = (x0 - mean) * rstd * gm.x + be.x;
    y.y = (x1 - mean) * rstd * gm.y + be.y;
    y.z = (x2 - mean) * rstd * gm.z + be.z;
    y.w = (x3 - mean) * rstd * gm.w + be.w;
    *(float4*)(out + (size_t)row * HID + t * 4) = y;
}

// ---------------------------------------------------------------------------
extern "C" void kernel_launch(void* const* d_in, const int* in_sizes, int n_in,
                              void* d_out, int out_size)
{
    const float* cnn = (const float*)d_in[0];
    const float* llm = (const float*)d_in[1];
    const float* Wq  = (const float*)d_in[2];
    const float* bq  = (const float*)d_in[3];
    const float* Wk  = (const float*)d_in[4];
    const float* bk  = (const float*)d_in[5];
    const float* Wv  = (const float*)d_in[6];
    const float* bv  = (const float*)d_in[7];
    const float* Wo  = (const float*)d_in[8];
    const float* bo  = (const float*)d_in[9];
    const float* ee  = (const float*)d_in[10];
    const float* me  = (const float*)d_in[11];
    const float* pe  = (const float*)d_in[12];
    const float* gamma = (const float*)d_in[13];
    const float* beta  = (const float*)d_in[14];
    float* out = (float*)d_out;

    cudaFuncSetAttribute(qkv_gemm,
                         cudaFuncAttributeMaxDynamicSharedMemorySize, GEMM_SMEM);
    cudaFuncSetAttribute(oproj_gemm,
                         cudaFuncAttributeMaxDynamicSharedMemorySize, GEMM_SMEM);

    conv_w<<<4096, 256>>>(Wq, Wk, Wv, Wo);
    build_aug<<<2 * MAUG, 256>>>(cnn, llm, ee, me, pe);

    {   // QKV projections (6 GEMMs)
        dim3 grid(HID / 256, (MAUG + 127) / 128, 6);
        qkv_gemm<<<grid, 256, GEMM_SMEM>>>(bq, bk, bv);
    }
    {   // cross-attention, both directions
        dim3 grid(SEQ / 128, NHEADS, 2 * Bz);
        attn_bf16<<<grid, 128>>>();
    }
    {   // output projection (2 GEMMs)
        dim3 grid(HID / 256, MOUT / 128, 2);
        oproj_gemm<<<grid, 256, GEMM_SMEM>>>(bo);
    }
    resid_ln<<<2 * Bz * SEQ, 256>>>(cnn, llm, gamma, beta, out);
}

// round 14
// speedup vs baseline: 1.6179x; 1.6179x over previous
#include <cuda_runtime.h>
#include <cuda_bf16.h>
#include <cstdint>
#include <cstddef>

// ---------------------------------------------------------------------------
// PhysicsInformedAttention — Round 14: GEMM 128x128 block / 64x32 warp tile
// (64 accum regs -> true 2 CTAs/SM, no spills). Attention = R12 (best).
// B=2, S=2048, HIDDEN=1024, NH=16, D=64, SA=2051. Physics biases cancel.
// ---------------------------------------------------------------------------

#define Bz 2
#define SEQ 2048
#define SA 2051
#define HID 1024
#define NHEADS 16
#define HD 64
#define MAUG (Bz * SA)   /* 4102 */
#define MOUT (Bz * SEQ)  /* 4096 */

__device__ __nv_bfloat16 g_augb[2 * MAUG * HID];
__device__ __nv_bfloat16 g_Wb  [4 * HID * HID];    // W bf16 [k][n] for q,k,v,o
__device__ __nv_bfloat16 g_Qb  [2 * MAUG * HID];
__device__ __nv_bfloat16 g_Kb  [2 * MAUG * HID];
__device__ __nv_bfloat16 g_Vb  [2 * MAUG * HID];
__device__ __nv_bfloat16 g_attb[2 * MOUT * HID];
__device__ float         g_O   [2 * MOUT * HID];

// ----------------------------- helpers -------------------------------------
__device__ __forceinline__ uint32_t pk(float a, float b) {
    __nv_bfloat162 h = __floats2bfloat162_rn(a, b);
    return *reinterpret_cast<uint32_t*>(&h);
}
__device__ __forceinline__ void ldsm4(uint32_t& r0, uint32_t& r1, uint32_t& r2,
                                      uint32_t& r3, const void* p) {
    uint32_t a = (uint32_t)__cvta_generic_to_shared(p);
    asm volatile("ldmatrix.sync.aligned.m8n8.x4.shared.b16 {%0,%1,%2,%3}, [%4];"
                 : "=r"(r0), "=r"(r1), "=r"(r2), "=r"(r3) : "r"(a));
}
__device__ __forceinline__ void ldsm4t(uint32_t& r0, uint32_t& r1, uint32_t& r2,
                                       uint32_t& r3, const void* p) {
    uint32_t a = (uint32_t)__cvta_generic_to_shared(p);
    asm volatile("ldmatrix.sync.aligned.m8n8.x4.trans.shared.b16 {%0,%1,%2,%3}, [%4];"
                 : "=r"(r0), "=r"(r1), "=r"(r2), "=r"(r3) : "r"(a));
}
__device__ __forceinline__ void mma_bf16(float* d, const uint32_t* a,
                                         const uint32_t* b) {
    asm volatile(
        "mma.sync.aligned.m16n8k16.row.col.f32.bf16.bf16.f32 "
        "{%0,%1,%2,%3}, {%4,%5,%6,%7}, {%8,%9}, {%0,%1,%2,%3};\n"
        : "+f"(d[0]), "+f"(d[1]), "+f"(d[2]), "+f"(d[3])
        : "r"(a[0]), "r"(a[1]), "r"(a[2]), "r"(a[3]), "r"(b[0]), "r"(b[1]));
}
__device__ __forceinline__ void cpa16(uint32_t dst, const void* src, bool ok) {
    int sz = ok ? 16 : 0;
    asm volatile("cp.async.cg.shared.global [%0], [%1], 16, %2;"
                 :: "r"(dst), "l"(src), "r"(sz) : "memory");
}
#define CPA_COMMIT() asm volatile("cp.async.commit_group;" ::: "memory")
#define CPA_WAIT1()  asm volatile("cp.async.wait_group 1;" ::: "memory")

// ---------------------------------------------------------------------------
// Kernel 0: fp32 -> bf16 convert of W (4 matrices)
// ---------------------------------------------------------------------------
__global__ __launch_bounds__(256) void conv_w(
    const float* __restrict__ Wq, const float* __restrict__ Wk,
    const float* __restrict__ Wv, const float* __restrict__ Wo)
{
    int i4 = blockIdx.x * 256 + threadIdx.x;
    int w  = i4 >> 18;
    int e  = i4 & 262143;
    const float* W = (w == 0) ? Wq : (w == 1) ? Wk : (w == 2) ? Wv : Wo;
    float4 v = ((const float4*)W)[e];
    *(uint2*)(g_Wb + (size_t)w * HID * HID + (size_t)e * 4) =
        make_uint2(pk(v.x, v.y), pk(v.z, v.w));
}

// ---------------------------------------------------------------------------
// Kernel 1: build augmented tensors -> bf16
// ---------------------------------------------------------------------------
__global__ __launch_bounds__(256) void build_aug(
    const float* __restrict__ cnn, const float* __restrict__ llm,
    const float* __restrict__ ee, const float* __restrict__ me,
    const float* __restrict__ pe)
{
    int row = blockIdx.x;
    int src = row / MAUG;
    int rem = row - src * MAUG;
    int b   = rem / SA;
    int s   = rem - b * SA;
    const float* p;
    if (s < SEQ) p = (src ? llm : cnn) + ((size_t)(b * SEQ + s)) * HID;
    else         p = (s == SEQ ? ee : (s == SEQ + 1 ? me : pe));
    __nv_bfloat16* dst = g_augb + (size_t)row * HID;
    int t = threadIdx.x;
    float4 v = *(const float4*)(p + t * 4);
    *(uint2*)(dst + t * 4) = make_uint2(pk(v.x, v.y), pk(v.z, v.w));
}

// ---------------------------------------------------------------------------
// bf16 GEMM: C[M,1024] = A[M,1024] @ W[1024,1024] + bias
// 128x128 block, kc=32, 8 warps 2x4, warp tile 64x32 (64 accum regs),
// 3-stage cp.async, 2 CTAs/SM.
// ---------------------------------------------------------------------------
#define AS_STRIDE 40
#define BS_STRIDE 136
#define AS_STG (128 * AS_STRIDE)   /* 5120 elems */
#define BS_STG (32 * BS_STRIDE)    /* 4352 elems */
#define GEMM_SMEM ((3 * AS_STG + 3 * BS_STG) * 2)

template <bool OUT_BF16>
__device__ __forceinline__ void gemm_body(
    const __nv_bfloat16* __restrict__ A, const __nv_bfloat16* __restrict__ Wb,
    const float* __restrict__ bias, void* Cout, int M)
{
    extern __shared__ char smraw[];
    __nv_bfloat16* Asm = (__nv_bfloat16*)smraw;          // [3][128][40]
    __nv_bfloat16* Bsm = Asm + 3 * AS_STG;               // [3][32][136]
    const uint32_t As_u = (uint32_t)__cvta_generic_to_shared(Asm);
    const uint32_t Bs_u = (uint32_t)__cvta_generic_to_shared(Bsm);

    const int tid  = threadIdx.x;
    const int lane = tid & 31;
    const int warp = tid >> 5;
    const int q = lane >> 2, r = lane & 3;
    const int g = lane >> 3, L = lane & 7;
    const int wm = warp >> 2, wn = warp & 3;
    const int bx = blockIdx.x, by = blockIdx.y;

    const int arow = tid >> 2, aseg = tid & 3;           // A: rows +0,+64
    const int brow = tid >> 4, bseg = tid & 15;          // B: rows +0,+16

    float acc[4][4][4];
#pragma unroll
    for (int i = 0; i < 4; i++)
#pragma unroll
        for (int j = 0; j < 4; j++)
#pragma unroll
            for (int k = 0; k < 4; k++) acc[i][j][k] = 0.f;

    auto fill = [&](int c, int s) {
#pragma unroll
        for (int i = 0; i < 2; i++) {
            const int row = arow + i * 64;
            const int gr  = by * 128 + row;
            const bool ok = gr < M;
            const __nv_bfloat16* src =
                A + (size_t)(ok ? gr : (M - 1)) * HID + c * 32 + aseg * 8;
            cpa16(As_u + (uint32_t)(s * AS_STG + row * AS_STRIDE + aseg * 8) * 2,
                  src, ok);
        }
#pragma unroll
        for (int i = 0; i < 2; i++) {
            const int row = brow + i * 16;
            const __nv_bfloat16* src =
                Wb + (size_t)(c * 32 + row) * HID + bx * 128 + bseg * 8;
            cpa16(Bs_u + (uint32_t)(s * BS_STG + row * BS_STRIDE + bseg * 8) * 2,
                  src, true);
        }
    };

    fill(0, 0); CPA_COMMIT();
    fill(1, 1); CPA_COMMIT();

    int st = 0;
    for (int it = 0; it < 32; it++) {
        CPA_WAIT1();
        __syncthreads();
        if (it + 2 < 32) {
            int s2 = st + 2; if (s2 >= 3) s2 -= 3;
            fill(it + 2, s2);
        }
        CPA_COMMIT();

        const __nv_bfloat16* Aps = Asm + st * AS_STG;
        const __nv_bfloat16* Bps = Bsm + st * BS_STG;
#pragma unroll
        for (int ks = 0; ks < 2; ks++) {
            const int k0 = ks * 16;
            uint32_t af[4][4];
#pragma unroll
            for (int mt = 0; mt < 4; mt++) {
                const int row = wm * 64 + mt * 16 + (g & 1) * 8 + L;
                ldsm4(af[mt][0], af[mt][1], af[mt][2], af[mt][3],
                      Aps + row * AS_STRIDE + k0 + (g >> 1) * 8);
            }
            uint32_t bf[4][2];
#pragma unroll
            for (int np = 0; np < 2; np++) {
                const int row = k0 + (g & 1) * 8 + L;
                const int col = wn * 32 + np * 16 + (g >> 1) * 8;
                uint32_t r0, r1, r2, r3;
                ldsm4t(r0, r1, r2, r3, Bps + row * BS_STRIDE + col);
                bf[np * 2][0] = r0; bf[np * 2][1] = r1;
                bf[np * 2 + 1][0] = r2; bf[np * 2 + 1][1] = r3;
            }
#pragma unroll
            for (int mt = 0; mt < 4; mt++)
#pragma unroll
                for (int nt = 0; nt < 4; nt++)
                    mma_bf16(acc[mt][nt], af[mt], bf[nt]);
        }
        if (++st >= 3) st = 0;
    }

    // epilogue
#pragma unroll
    for (int mt = 0; mt < 4; mt++) {
#pragma unroll
        for (int nt = 0; nt < 4; nt++) {
            const int row0 = by * 128 + wm * 64 + mt * 16 + q;
            const int col  = bx * 128 + wn * 32 + nt * 8 + 2 * r;
            const float b0 = bias[col], b1 = bias[col + 1];
            const float* a = acc[mt][nt];
            if constexpr (OUT_BF16) {
                __nv_bfloat16* C = (__nv_bfloat16*)Cout;
                if (row0 < M)
                    *(uint32_t*)(C + (size_t)row0 * HID + col) = pk(a[0] + b0, a[1] + b1);
                if (row0 + 8 < M)
                    *(uint32_t*)(C + (size_t)(row0 + 8) * HID + col) = pk(a[2] + b0, a[3] + b1);
            } else {
                float* C = (float*)Cout;
                if (row0 < M)
                    *(float2*)(C + (size_t)row0 * HID + col) =
                        make_float2(a[0] + b0, a[1] + b1);
                if (row0 + 8 < M)
                    *(float2*)(C + (size_t)(row0 + 8) * HID + col) =
                        make_float2(a[2] + b0, a[3] + b1);
            }
        }
    }
}

__global__ __launch_bounds__(256, 2) void qkv_gemm(
    const float* __restrict__ bq, const float* __restrict__ bk,
    const float* __restrict__ bv)
{
    int z = blockIdx.z;
    int src = z / 3, w = z - src * 3;
    const __nv_bfloat16* A = g_augb + (size_t)src * MAUG * HID;
    const __nv_bfloat16* Wb = g_Wb + (size_t)w * HID * HID;
    const float* bp = (w == 0) ? bq : (w == 1) ? bk : bv;
    __nv_bfloat16* C = ((w == 0) ? g_Qb : (w == 1) ? g_Kb : g_Vb)
                       + (size_t)src * MAUG * HID;
    gemm_body<true>(A, Wb, bp, C, MAUG);
}

__global__ __launch_bounds__(256, 2) void oproj_gemm(const float* __restrict__ bo)
{
    int dir = blockIdx.z;
    gemm_body<false>(g_attb + (size_t)dir * MOUT * HID,
                     g_Wb + (size_t)3 * HID * HID, bo,
                     g_O + (size_t)dir * MOUT * HID, MOUT);
}

// ---------------------------------------------------------------------------
// Flash attention: 4 warps x 32 q-rows, Bc=32, register-resident P,
// 3-stage cp.async, static smem, 3 CTAs/SM (unchanged from R12 best).
// ---------------------------------------------------------------------------
__global__ __launch_bounds__(128, 3) void attn_bf16()
{
    __shared__ alignas(16) __nv_bfloat16 Kst[3][32][72];
    __shared__ alignas(16) __nv_bfloat16 Vst[3][32][72];

    const int tid  = threadIdx.x;
    const int lane = tid & 31;
    const int warp = tid >> 5;        // 0..3, owns q rows [32w, 32w+32)
    const int q = lane >> 2, r = lane & 3;
    const int g = lane >> 3, L = lane & 7;
    const int m0 = warp * 32;

    const int qt  = blockIdx.x;
    const int h   = blockIdx.y;
    const int dir = blockIdx.z >> 1;
    const int b   = blockIdx.z & 1;

    const __nv_bfloat16* qp =
        g_Qb + ((size_t)((dir * Bz + b) * SA) + qt * 128 + m0) * HID + h * HD;
    const size_t kvbase = ((size_t)(((dir ^ 1) * Bz + b) * SA)) * HID + h * HD;

    const uint32_t K_u = (uint32_t)__cvta_generic_to_shared(&Kst[0][0][0]);
    const uint32_t V_u = (uint32_t)__cvta_generic_to_shared(&Vst[0][0][0]);
    const int frow = tid >> 2, fseg = tid & 3;   // 128 thr: row 0..31, 2 segs each

    auto fill = [&](int t, int s) {
        const int key = t * 32 + frow;
        const bool ok = key < SA;
        const size_t rb = kvbase + (size_t)(ok ? key : 0) * HID;
#pragma unroll
        for (int i = 0; i < 2; i++) {
            const int seg = fseg + i * 4;
            const uint32_t d = (uint32_t)(s * 32 * 72 + frow * 72 + seg * 8) * 2;
            cpa16(K_u + d, g_Kb + rb + seg * 8, ok);
            cpa16(V_u + d, g_Vb + rb + seg * 8, ok);
        }
    };

    // persistent Q fragments (2 m-tiles x 4 k-steps)
    uint32_t aQ[2][4][4];
#pragma unroll
    for (int mt = 0; mt < 2; mt++) {
        const __nv_bfloat16* qpm = qp + (size_t)(mt * 16) * HID;
#pragma unroll
        for (int ks = 0; ks < 4; ks++) {
            const int c0 = ks * 16 + 2 * r;
            aQ[mt][ks][0] = *(const uint32_t*)(qpm + (size_t)q * HID + c0);
            aQ[mt][ks][1] = *(const uint32_t*)(qpm + (size_t)(q + 8) * HID + c0);
            aQ[mt][ks][2] = *(const uint32_t*)(qpm + (size_t)q * HID + c0 + 8);
            aQ[mt][ks][3] = *(const uint32_t*)(qpm + (size_t)(q + 8) * HID + c0 + 8);
        }
    }

    float o[2][8][4];
#pragma unroll
    for (int mt = 0; mt < 2; mt++)
#pragma unroll
        for (int i = 0; i < 8; i++)
#pragma unroll
            for (int j = 0; j < 4; j++) o[mt][i][j] = 0.f;
    float l0[2] = {0.f, 0.f}, l1[2] = {0.f, 0.f};

    fill(0, 0); CPA_COMMIT();
    fill(1, 1); CPA_COMMIT();

    int st = 0;
    for (int kt = 0; kt < 65; kt++) {
        CPA_WAIT1();
        __syncthreads();
        if (kt + 2 < 65) {
            int s2 = st + 2; if (s2 >= 3) s2 -= 3;
            fill(kt + 2, s2);
        }
        CPA_COMMIT();

        // ---- S = Q @ K^T : 32 q x 32 keys per warp; K frags shared by mt ----
        float sAcc[2][4][4];
#pragma unroll
        for (int mt = 0; mt < 2; mt++)
#pragma unroll
            for (int i = 0; i < 4; i++)
#pragma unroll
                for (int j = 0; j < 4; j++) sAcc[mt][i][j] = 0.f;
#pragma unroll
        for (int ks = 0; ks < 4; ks++) {
            const int k0 = ks * 16;
            uint32_t bk_[4][2];
#pragma unroll
            for (int half = 0; half < 2; half++) {
                const int row = half * 16 + (g >> 1) * 8 + L;
                const int col = k0 + (g & 1) * 8;
                uint32_t r0, r1, r2, r3;
                ldsm4(r0, r1, r2, r3, &Kst[st][row][col]);
                bk_[half * 2][0] = r0; bk_[half * 2][1] = r1;
                bk_[half * 2 + 1][0] = r2; bk_[half * 2 + 1][1] = r3;
            }
#pragma unroll
            for (int mt = 0; mt < 2; mt++)
#pragma unroll
                for (int nt = 0; nt < 4; nt++)
                    mma_bf16(sAcc[mt][nt], aQ[mt][ks], bk_[nt]);
        }

        // ---- P = exp(S/8) in registers -> A fragments ----
        uint32_t aP[2][2][4];
        if (kt < 64) {
#pragma unroll
            for (int mt = 0; mt < 2; mt++) {
#pragma unroll
                for (int nt = 0; nt < 4; nt++) {
                    float e0 = __expf(sAcc[mt][nt][0] * 0.125f);
                    float e1 = __expf(sAcc[mt][nt][1] * 0.125f);
                    float e2 = __expf(sAcc[mt][nt][2] * 0.125f);
                    float e3 = __expf(sAcc[mt][nt][3] * 0.125f);
                    l0[mt] += e0 + e1;
                    l1[mt] += e2 + e3;
                    aP[mt][nt >> 1][(nt & 1) ? 2 : 0] = pk(e0, e1);
                    aP[mt][nt >> 1][(nt & 1) ? 3 : 1] = pk(e2, e3);
                }
            }
        } else {
            const int kb = kt * 32;
#pragma unroll
            for (int mt = 0; mt < 2; mt++) {
#pragma unroll
                for (int nt = 0; nt < 4; nt++) {
                    const int key0 = kb + nt * 8 + 2 * r;
                    float e0 = (key0     < SA) ? __expf(sAcc[mt][nt][0] * 0.125f) : 0.f;
                    float e1 = (key0 + 1 < SA) ? __expf(sAcc[mt][nt][1] * 0.125f) : 0.f;
                    float e2 = (key0     < SA) ? __expf(sAcc[mt][nt][2] * 0.125f) : 0.f;
                    float e3 = (key0 + 1 < SA) ? __expf(sAcc[mt][nt][3] * 0.125f) : 0.f;
                    l0[mt] += e0 + e1;
                    l1[mt] += e2 + e3;
                    aP[mt][nt >> 1][(nt & 1) ? 2 : 0] = pk(e0, e1);
                    aP[mt][nt >> 1][(nt & 1) ? 3 : 1] = pk(e2, e3);
                }
            }
        }

        // ---- O += P @ V : V frags shared by mt ----
#pragma unroll
        for (int p = 0; p < 2; p++) {
            const int k0 = p * 16;
#pragma unroll
            for (int db = 0; db < 4; db++) {
                const int row = k0 + (g & 1) * 8 + L;
                const int col = db * 16 + (g >> 1) * 8;
                uint32_t r0, r1, r2, r3;
                ldsm4t(r0, r1, r2, r3, &Vst[st][row][col]);
                uint32_t b0[2] = {r0, r1};
                uint32_t b1[2] = {r2, r3};
#pragma unroll
                for (int mt = 0; mt < 2; mt++) {
                    mma_bf16(o[mt][db * 2], aP[mt][p], b0);
                    mma_bf16(o[mt][db * 2 + 1], aP[mt][p], b1);
                }
            }
        }
        if (++st >= 3) st = 0;
    }

    // ---- finalize per m-tile: quad row-sums, scale, bf16 store ----
#pragma unroll
    for (int mt = 0; mt < 2; mt++) {
        float a0 = l0[mt], a1 = l1[mt];
        a0 += __shfl_xor_sync(0xFFFFFFFFu, a0, 1);
        a0 += __shfl_xor_sync(0xFFFFFFFFu, a0, 2);
        a1 += __shfl_xor_sync(0xFFFFFFFFu, a1, 1);
        a1 += __shfl_xor_sync(0xFFFFFFFFu, a1, 2);
        const float inv0 = 1.0f / a0;
        const float inv1 = 1.0f / a1;

        __nv_bfloat16* op =
            g_attb + ((size_t)((dir * Bz + b) * SEQ) + qt * 128 + m0 + mt * 16) * HID
            + h * HD;
#pragma unroll
        for (int nt2 = 0; nt2 < 8; nt2++) {
            const int c = nt2 * 8 + 2 * r;
            *(uint32_t*)(op + (size_t)q * HID + c) =
                pk(o[mt][nt2][0] * inv0, o[mt][nt2][1] * inv0);
            *(uint32_t*)(op + (size_t)(q + 8) * HID + c) =
                pk(o[mt][nt2][2] * inv1, o[mt][nt2][3] * inv1);
        }
    }
}

// ---------------------------------------------------------------------------
// Kernel 4: residual + LayerNorm (fp32)
// ---------------------------------------------------------------------------
__global__ __launch_bounds__(256) void resid_ln(
    const float* __restrict__ cnn, const float* __restrict__ llm,
    const float* __restrict__ gamma, const float* __restrict__ beta,
    float* __restrict__ out)
{
    int row = blockIdx.x;
    int dir = row >> 12;
    int b   = (row >> 11) & 1;
    int s   = row & (SEQ - 1);
    const float* resid = (dir ? llm : cnn) + ((size_t)(b * SEQ + s)) * HID;
    const float* op = g_O + (size_t)row * HID;
    int t = threadIdx.x;

    float4 rv = *(const float4*)(resid + t * 4);
    float4 ov = *(const float4*)(op + t * 4);
    float x0 = rv.x + ov.x, x1 = rv.y + ov.y, x2 = rv.z + ov.z, x3 = rv.w + ov.w;
    float s1 = (x0 + x1) + (x2 + x3);
    float s2 = x0 * x0 + x1 * x1 + x2 * x2 + x3 * x3;
#pragma unroll
    for (int off = 16; off; off >>= 1) {
        s1 += __shfl_xor_sync(0xFFFFFFFFu, s1, off);
        s2 += __shfl_xor_sync(0xFFFFFFFFu, s2, off);
    }
    __shared__ float sm1[8], sm2[8];
    int wp = t >> 5, lane = t & 31;
    if (lane == 0) { sm1[wp] = s1; sm2[wp] = s2; }
    __syncthreads();
    if (t == 0) {
        float a = 0.f, c = 0.f;
#pragma unroll
        for (int i = 0; i < 8; i++) { a += sm1[i]; c += sm2[i]; }
        sm1[0] = a; sm2[0] = c;
    }
    __syncthreads();
    float mean = sm1[0] * (1.0f / HID);
    float var  = sm2[0] * (1.0f / HID) - mean * mean;
    float rstd = rsqrtf(var + 1e-5f);

    float4 gm = *(const float4*)(gamma + t * 4);
    float4 be = *(const float4*)(beta + t * 4);
    float4 y;
    y.x = (x0 - mean) * rstd * gm.x + be.x;
    y.y = (x1 - mean) * rstd * gm.y + be.y;
    y.z = (x2 - mean) * rstd * gm.z + be.z;
    y.w = (x3 - mean) * rstd * gm.w + be.w;
    *(float4*)(out + (size_t)row * HID + t * 4) = y;
}

// ---------------------------------------------------------------------------
extern "C" void kernel_launch(void* const* d_in, const int* in_sizes, int n_in,
                              void* d_out, int out_size)
{
    const float* cnn = (const float*)d_in[0];
    const float* llm = (const float*)d_in[1];
    const float* Wq  = (const float*)d_in[2];
    const float* bq  = (const float*)d_in[3];
    const float* Wk  = (const float*)d_in[4];
    const float* bk  = (const float*)d_in[5];
    const float* Wv  = (const float*)d_in[6];
    const float* bv  = (const float*)d_in[7];
    const float* Wo  = (const float*)d_in[8];
    const float* bo  = (const float*)d_in[9];
    const float* ee  = (const float*)d_in[10];
    const float* me  = (const float*)d_in[11];
    const float* pe  = (const float*)d_in[12];
    const float* gamma = (const float*)d_in[13];
    const float* beta  = (const float*)d_in[14];
    float* out = (float*)d_out;

    cudaFuncSetAttribute(qkv_gemm,
                         cudaFuncAttributeMaxDynamicSharedMemorySize, GEMM_SMEM);
    cudaFuncSetAttribute(oproj_gemm,
                         cudaFuncAttributeMaxDynamicSharedMemorySize, GEMM_SMEM);

    conv_w<<<4096, 256>>>(Wq, Wk, Wv, Wo);
    build_aug<<<2 * MAUG, 256>>>(cnn, llm, ee, me, pe);

    {   // QKV projections (6 GEMMs)
        dim3 grid(HID / 128, (MAUG + 127) / 128, 6);
        qkv_gemm<<<grid, 256, GEMM_SMEM>>>(bq, bk, bv);
    }
    {   // cross-attention, both directions
        dim3 grid(SEQ / 128, NHEADS, 2 * Bz);
        attn_bf16<<<grid, 128>>>();
    }
    {   // output projection (2 GEMMs)
        dim3 grid(HID / 128, MOUT / 128, 2);
        oproj_gemm<<<grid, 256, GEMM_SMEM>>>(bo);
    }
    resid_ln<<<2 * Bz * SEQ, 256>>>(cnn, llm, gamma, beta, out);
}